// round 16
// baseline (speedup 1.0000x reference)
#include <cuda_runtime.h>
#include <cuda_bf16.h>
#include <cstdint>

// NT-Xent fused: N=4096, Z=128, T=0.5
#define TWO_N 8192
#define ZD 128
#define INV_T 2.0f
// exp(sim/T) = 2^(sim * INV_T * log2(e)); fold sqrt of the scale into each
// stored bf16 row so the MMA accumulator is directly the ex2 argument.
#define SQRT_EXP_SCALE 1.6986435651438231f   // sqrt(2 * log2(e))
#define LN2F 0.6931471805599453f

#define BM 128
#define BN 128
#define ROW_TILES (TWO_N / BM)                       // 64
#define NUM_TILES (ROW_TILES * (ROW_TILES + 1) / 2)  // 2080 (upper triangle)
#define NUM_CTAS 304                     // persistent: 2 per SM x 152 SMs
#define STRIDE 136                       // bf16 elems per smem row (128 + 8 pad)
#define Q_ELEMS (32 * STRIDE)            // 4352 (32-row quarter strip)
#define Q_BYTES (Q_ELEMS * 2)            // 8704
#define B_ELEMS (BM * STRIDE)            // 17408 (full 128-row B strip)
// smem: B strip + per-group A double buffers (4 groups x 2 buffers x 32 rows)
#define SMEM_SZ ((B_ELEMS + 8 * Q_ELEMS) * 2)        // 104448

// Scratch (device globals — no allocation allowed)
__device__ __nv_bfloat16 g_nrep_bf16[TWO_N * ZD];
__device__ float         g_rowsum  [TWO_N];
__device__ float         g_pos     [TWO_N];
__device__ unsigned int  g_ticket;

// ---------------------------------------------------------------------------
// Kernel 1: ONE WARP per positive pair (j, j+N). float4 loads, pure shfl
// reductions (no smem/syncthreads). Emits pre-scaled bf16 rows, fp32
// positives, zero rowsums. 512 blocks x 256 threads = 4096 warps.
// ---------------------------------------------------------------------------
__global__ void normalize_pos_kernel(const float* __restrict__ z1,
                                     const float* __restrict__ z2) {
    int j = (blockIdx.x * blockDim.x + threadIdx.x) >> 5;   // pair 0..4095
    int lane = threadIdx.x & 31;

    const float4 v = ((const float4*)z1)[(size_t)j * 32 + lane];
    const float4 p = ((const float4*)z2)[(size_t)j * 32 + lane];

    float s0 = v.x*v.x + v.y*v.y + v.z*v.z + v.w*v.w;
    float s1 = p.x*p.x + p.y*p.y + p.z*p.z + p.w*p.w;
    float s2 = v.x*p.x + v.y*p.y + v.z*p.z + v.w*p.w;
    #pragma unroll
    for (int o = 16; o > 0; o >>= 1) {
        s0 += __shfl_xor_sync(0xFFFFFFFFu, s0, o);
        s1 += __shfl_xor_sync(0xFFFFFFFFu, s1, o);
        s2 += __shfl_xor_sync(0xFFFFFFFFu, s2, o);
    }
    float invA = 1.0f / fmaxf(sqrtf(s0), 1e-8f);
    float invB = 1.0f / fmaxf(sqrtf(s1), 1e-8f);
    float sa = invA * SQRT_EXP_SCALE;
    float sb = invB * SQRT_EXP_SCALE;

    uint2 oa, ob;
    {
        __nv_bfloat162 h0 = __float22bfloat162_rn(make_float2(v.x * sa, v.y * sa));
        __nv_bfloat162 h1 = __float22bfloat162_rn(make_float2(v.z * sa, v.w * sa));
        oa.x = *(uint32_t*)&h0; oa.y = *(uint32_t*)&h1;
        __nv_bfloat162 g0 = __float22bfloat162_rn(make_float2(p.x * sb, p.y * sb));
        __nv_bfloat162 g1 = __float22bfloat162_rn(make_float2(p.z * sb, p.w * sb));
        ob.x = *(uint32_t*)&g0; ob.y = *(uint32_t*)&g1;
    }
    ((uint2*)(g_nrep_bf16 + (size_t)j * ZD))[lane] = oa;
    ((uint2*)(g_nrep_bf16 + (size_t)(j + TWO_N/2) * ZD))[lane] = ob;

    if (lane == 0) {
        float pos = s2 * invA * invB;
        g_pos[j] = pos;
        g_pos[j + TWO_N/2] = pos;
        g_rowsum[j] = 0.0f;
        g_rowsum[j + TWO_N/2] = 0.0f;
        if (j == 0) g_ticket = 0u;
    }
}

// ---------------------------------------------------------------------------
// cp.async loaders. Full B strip: 512 threads. Quarter A strip: 128 threads.
// ---------------------------------------------------------------------------
__device__ __forceinline__ void load_b(__nv_bfloat16* dst, int rowBase, int tid) {
    #pragma unroll
    for (int it = 0; it < 4; it++) {
        int i2 = it * 512 + tid;          // 2048 16B-chunks
        int rr = i2 >> 4, c = i2 & 15;
        uint32_t d = (uint32_t)__cvta_generic_to_shared(dst + rr * STRIDE + c * 8);
        const void* g = g_nrep_bf16 + (size_t)(rowBase + rr) * ZD + c * 8;
        asm volatile("cp.async.cg.shared.global [%0], [%1], 16;" :: "r"(d), "l"(g));
    }
}
__device__ __forceinline__ void load_a_q(__nv_bfloat16* dst, int rowBase, int qtid) {
    #pragma unroll
    for (int it = 0; it < 4; it++) {
        int i2 = it * 128 + qtid;         // 512 16B-chunks (32 rows)
        int rr = i2 >> 4, c = i2 & 15;
        uint32_t d = (uint32_t)__cvta_generic_to_shared(dst + rr * STRIDE + c * 8);
        const void* g = g_nrep_bf16 + (size_t)(rowBase + rr) * ZD + c * 8;
        asm volatile("cp.async.cg.shared.global [%0], [%1], 16;" :: "r"(d), "l"(g));
    }
}

// ---------------------------------------------------------------------------
// Per-tile epilogue (DIAG templated): ex2 of acc (scale pre-folded), optional
// self-diag mask; row flush = 2 SHFL + ONE red.global per row (single L2
// atomic op per address — per-address serialization is the L2 constraint);
// column sums ride in colacc registers.
// ---------------------------------------------------------------------------
template<bool DIAG>
__device__ __forceinline__ void epilogue(float (&acc)[2][4][4], float (&colacc)[8],
                                         int rowBase, int colBase,
                                         int wn, int lane) {
    int g = lane >> 2, t = lane & 3;

    #pragma unroll
    for (int mt = 0; mt < 2; mt++) {
        #pragma unroll
        for (int hh = 0; hh < 2; hh++) {
            int i = rowBase + mt * 16 + hh * 8 + g;
            float s = 0.0f;
            #pragma unroll
            for (int nt = 0; nt < 4; nt++) {
                #pragma unroll
                for (int e = 0; e < 2; e++) {
                    float ex;
                    asm("ex2.approx.f32 %0, %1;" : "=f"(ex)
                        : "f"(acc[mt][nt][hh * 2 + e]));
                    if (DIAG) {
                        int j = colBase + wn * 32 + t * 2 + nt * 8 + e;
                        if (i == j) ex = 0.0f;
                    }
                    s += ex;
                    if (!DIAG) colacc[nt * 2 + e] += ex;
                }
            }
            s += __shfl_xor_sync(0xFFFFFFFFu, s, 1);
            s += __shfl_xor_sync(0xFFFFFFFFu, s, 2);
            if (t == 0)
                asm volatile("red.global.add.f32 [%0], %1;"
                             :: "l"(&g_rowsum[i]), "f"(s) : "memory");
        }
    }
}

// Flush accumulated column sums for column strip colBase, then zero them.
__device__ __forceinline__ void flush_colacc(float (&colacc)[8], int colBase,
                                             int wn, int lane) {
    int g = lane >> 2, t = lane & 3;
    #pragma unroll
    for (int c = 0; c < 8; c++) {
        float v = colacc[c];
        v += __shfl_xor_sync(0xFFFFFFFFu, v, 4);
        v += __shfl_xor_sync(0xFFFFFFFFu, v, 8);
        v += __shfl_xor_sync(0xFFFFFFFFu, v, 16);
        colacc[c] = v;
    }
    if (g == 0) {
        int jbase = colBase + wn * 32 + t * 2;
        #pragma unroll
        for (int c = 0; c < 8; c++) {
            int j = jbase + (c >> 1) * 8 + (c & 1);
            asm volatile("red.global.add.f32 [%0], %1;"
                         :: "l"(&g_rowsum[j]), "f"(colacc[c]) : "memory");
        }
    }
    #pragma unroll
    for (int c = 0; c < 8; c++) colacc[c] = 0.0f;
}

// ---------------------------------------------------------------------------
// Kernel 2: PERSISTENT fused sim GEMM (PDL consumer). Prologue (triangle
// decode + address setup) runs concurrently with normalize_pos_kernel;
// griddepcontrol.wait gates the first dependent load. Column-major triangle
// walk, CTA split into FOUR independent 128-thread groups (named barriers),
// per-group double-buffered A, shared per-column B.
// ---------------------------------------------------------------------------
__global__ void __launch_bounds__(512, 2) simgemm_kernel(float* __restrict__ out) {
    extern __shared__ __nv_bfloat16 smem[];
    __nv_bfloat16* sB = smem;                            // full column strip
    int tid = threadIdx.x;
    int wid = tid >> 5, lane = tid & 31;
    int grp = wid >> 2;                  // group 0..3 (owns rows grp*32..+32)
    int wn  = wid & 3;                   // n-warp within group (SMSP spread)
    int qtid = tid & 127;                // thread within group
    __nv_bfloat16* sA = smem + B_ELEMS + grp * 2 * Q_ELEMS;  // parity buffers

    // ---- Prologue (independent of producer kernel) ----
    const int base = NUM_TILES / NUM_CTAS;      // 6
    const int rem  = NUM_TILES % NUM_CTAS;      // 256
    int bidx = blockIdx.x;
    int start = bidx * base + (bidx < rem ? bidx : rem);
    int count = base + (bidx < rem ? 1 : 0);

    // Decode start -> (tx, ty): column tx holds tiles ty in [0, tx]
    int tx = (int)((sqrtf(8.0f * (float)start + 1.0f) - 1.0f) * 0.5f);
    while (tx * (tx + 1) / 2 > start) tx--;
    while ((tx + 1) * (tx + 2) / 2 <= start) tx++;
    int ty = start - tx * (tx + 1) / 2;

    // ldmatrix base addresses (per lane); A offset adds parity*Q_BYTES
    uint32_t aAddr[2];
    #pragma unroll
    for (int mt = 0; mt < 2; mt++) {
        int row = mt * 16 + (lane & 15);                 // 0..31 in strip
        int k = (lane >> 4) * 8;
        aAddr[mt] = (uint32_t)__cvta_generic_to_shared(sA + row * STRIDE + k);
    }
    uint32_t bAddr[2];
    #pragma unroll
    for (int ntp = 0; ntp < 2; ntp++) {
        int n = wn * 32 + ntp * 16 + ((lane >> 4) & 1) * 8 + (lane & 7);
        int k = ((lane >> 3) & 1) * 8;
        bAddr[ntp] = (uint32_t)__cvta_generic_to_shared(sB + n * STRIDE + k);
    }

    float colacc[8];
    #pragma unroll
    for (int c = 0; c < 8; c++) colacc[c] = 0.0f;

    int barid = 1 + grp;    // named barrier per group (0 reserved for CTA)

    // ---- PDL: wait for normalize_pos_kernel's memory before loading ----
    asm volatile("griddepcontrol.wait;" ::: "memory");

    // Initial loads: B(tx) by all threads, A quarter by each group; one group
    load_b(sB, tx * BN, tid);
    load_a_q(sA, ty * BM + grp * 32, qtid);
    asm volatile("cp.async.commit_group;" ::: "memory");

    #pragma unroll 1
    for (int t = 0; t < count; t++) {
        uint32_t aOff = (uint32_t)(t & 1) * Q_BYTES;
        int nty = ty + 1, ntx = tx;
        if (nty > tx) { ntx = tx + 1; nty = 0; }
        bool more = (t + 1 < count);

        // Wait for this tile's A (+B at transitions); prefetched -> usually free
        asm volatile("cp.async.wait_group 0;" ::: "memory");
        asm volatile("bar.sync %0, 128;" :: "r"(barid) : "memory");

        // Same column: prefetch this group's next A into the alternate buffer
        if (more && ntx == tx) {
            load_a_q(sA + ((t + 1) & 1) * Q_ELEMS, nty * BM + grp * 32, qtid);
            asm volatile("cp.async.commit_group;" ::: "memory");
        }

        float acc[2][4][4];
        #pragma unroll
        for (int mt = 0; mt < 2; mt++)
            #pragma unroll
            for (int nt = 0; nt < 4; nt++)
                #pragma unroll
                for (int e = 0; e < 4; e++) acc[mt][nt][e] = 0.0f;

        // ---- Mainloop: 8 k-steps of k16
        #pragma unroll
        for (int ks = 0; ks < 8; ks++) {
            uint32_t a[2][4];
            #pragma unroll
            for (int mt = 0; mt < 2; mt++)
                asm volatile("ldmatrix.sync.aligned.m8n8.x4.shared.b16 {%0,%1,%2,%3}, [%4];"
                    : "=r"(a[mt][0]), "=r"(a[mt][1]), "=r"(a[mt][2]), "=r"(a[mt][3])
                    : "r"(aAddr[mt] + aOff + ks * 32));
            uint32_t b[4][2];
            #pragma unroll
            for (int ntp = 0; ntp < 2; ntp++)
                asm volatile("ldmatrix.sync.aligned.m8n8.x4.shared.b16 {%0,%1,%2,%3}, [%4];"
                    : "=r"(b[2*ntp][0]), "=r"(b[2*ntp][1]),
                      "=r"(b[2*ntp+1][0]), "=r"(b[2*ntp+1][1])
                    : "r"(bAddr[ntp] + ks * 32));
            #pragma unroll
            for (int mt = 0; mt < 2; mt++)
                #pragma unroll
                for (int nt = 0; nt < 4; nt++)
                    asm volatile(
                        "mma.sync.aligned.m16n8k16.row.col.f32.bf16.bf16.f32 "
                        "{%0,%1,%2,%3}, {%4,%5,%6,%7}, {%8,%9}, {%0,%1,%2,%3};"
                        : "+f"(acc[mt][nt][0]), "+f"(acc[mt][nt][1]),
                          "+f"(acc[mt][nt][2]), "+f"(acc[mt][nt][3])
                        : "r"(a[mt][0]), "r"(a[mt][1]), "r"(a[mt][2]), "r"(a[mt][3]),
                          "r"(b[nt][0]), "r"(b[nt][1]));
        }

        int rowBase = ty * BM + grp * 32;
        if (ty == tx) {
            epilogue<true >(acc, colacc, rowBase, tx * BN, wn, lane);
            flush_colacc(colacc, tx * BN, wn, lane);   // column complete
        } else {
            epilogue<false>(acc, colacc, rowBase, tx * BN, wn, lane);
        }

        // Column transition: rejoin the full CTA, reload B (+ own A quarter)
        if (more && ntx != tx) {
            __syncthreads();
            load_b(sB, ntx * BN, tid);
            load_a_q(sA + ((t + 1) & 1) * Q_ELEMS, nty * BM + grp * 32, qtid);
            asm volatile("cp.async.commit_group;" ::: "memory");
        }
        ty = nty; tx = ntx;
    }

    // Flush any partial column left at chunk end (zeros if already flushed)
    flush_colacc(colacc, (ty == 0 ? tx - 1 : tx) * BN, wn, lane);

    // ---- Ticket: last CTA computes the scalar loss (fast log2)
    __shared__ bool is_last;
    __syncthreads();
    if (tid == 0) {
        __threadfence();
        unsigned int tk = atomicInc(&g_ticket, 0xFFFFFFFFu);
        is_last = (tk == (unsigned int)(NUM_CTAS - 1));
    }
    __syncthreads();
    if (is_last) {
        __threadfence();
        float acc2 = 0.0f;
        #pragma unroll 4
        for (int i = tid; i < TWO_N; i += 512)
            acc2 += __log2f(__ldcg(&g_rowsum[i])) * LN2F - g_pos[i] * INV_T;
        #pragma unroll
        for (int o = 16; o > 0; o >>= 1)
            acc2 += __shfl_xor_sync(0xFFFFFFFFu, acc2, o);
        __shared__ float sred[16];
        if ((tid & 31) == 0) sred[tid >> 5] = acc2;
        __syncthreads();
        if (tid == 0) {
            float tot = 0.0f;
            #pragma unroll
            for (int w = 0; w < 16; w++) tot += sred[w];
            out[0] = tot * (1.0f / (float)TWO_N);
        }
    }
}

// ---------------------------------------------------------------------------
extern "C" void kernel_launch(void* const* d_in, const int* in_sizes, int n_in,
                              void* d_out, int out_size) {
    const float* z1 = (const float*)d_in[0];
    const float* z2 = (const float*)d_in[1];

    cudaFuncSetAttribute(simgemm_kernel,
                         cudaFuncAttributeMaxDynamicSharedMemorySize, SMEM_SZ);

    normalize_pos_kernel<<<512, 256>>>(z1, z2);

    // PDL launch: simgemm's prologue overlaps normalize; griddepcontrol.wait
    // inside the kernel provides the ordering on g_nrep_bf16/g_pos/g_rowsum.
    cudaLaunchConfig_t cfg = {};
    cfg.gridDim = dim3(NUM_CTAS, 1, 1);
    cfg.blockDim = dim3(512, 1, 1);
    cfg.dynamicSmemBytes = SMEM_SZ;
    cfg.stream = 0;
    cudaLaunchAttribute attrs[1];
    attrs[0].id = cudaLaunchAttributeProgrammaticStreamSerialization;
    attrs[0].val.programmaticStreamSerializationAllowed = 1;
    cfg.attrs = attrs;
    cfg.numAttrs = 1;
    cudaLaunchKernelEx(&cfg, simgemm_kernel, (float*)d_out);
}

// round 17
// speedup vs baseline: 1.0060x; 1.0060x over previous
#include <cuda_runtime.h>
#include <cuda_bf16.h>
#include <cstdint>

// NT-Xent fused: N=4096, Z=128, T=0.5
#define TWO_N 8192
#define ZD 128
#define INV_T 2.0f
// exp(sim/T) = 2^(sim * INV_T * log2(e)); fold sqrt of the scale into each
// stored bf16 row so the MMA accumulator is directly the ex2 argument.
#define SQRT_EXP_SCALE 1.6986435651438231f   // sqrt(2 * log2(e))
#define LN2F 0.6931471805599453f

#define BM 128
#define BN 128
#define ROW_TILES (TWO_N / BM)                       // 64
#define NUM_TILES (ROW_TILES * (ROW_TILES + 1) / 2)  // 2080 (upper triangle)
#define NUM_CTAS 304                     // persistent: 2 per SM x 152 SMs
#define STRIDE 136                       // bf16 elems per smem row (128 + 8 pad)
#define Q_ELEMS (32 * STRIDE)            // 4352 (32-row quarter strip)
#define Q_BYTES (Q_ELEMS * 2)            // 8704
#define B_ELEMS (BM * STRIDE)            // 17408 (full 128-row B strip)
// smem: B strip + per-group A double buffers (4 groups x 2 buffers x 32 rows)
#define SMEM_SZ ((B_ELEMS + 8 * Q_ELEMS) * 2)        // 104448

// Scratch (device globals — no allocation allowed)
__device__ __nv_bfloat16 g_nrep_bf16[TWO_N * ZD];
__device__ float         g_rowsum  [TWO_N];
__device__ float         g_pos     [TWO_N];
__device__ unsigned int  g_ticket;

// ---------------------------------------------------------------------------
// Kernel 1: ONE WARP per positive pair (j, j+N). float4 loads, pure shfl
// reductions (no smem/syncthreads). Emits pre-scaled bf16 rows, fp32
// positives, zero rowsums. 512 blocks x 256 threads = 4096 warps.
// ---------------------------------------------------------------------------
__global__ void normalize_pos_kernel(const float* __restrict__ z1,
                                     const float* __restrict__ z2) {
    int j = (blockIdx.x * blockDim.x + threadIdx.x) >> 5;   // pair 0..4095
    int lane = threadIdx.x & 31;

    const float4 v = ((const float4*)z1)[(size_t)j * 32 + lane];
    const float4 p = ((const float4*)z2)[(size_t)j * 32 + lane];

    float s0 = v.x*v.x + v.y*v.y + v.z*v.z + v.w*v.w;
    float s1 = p.x*p.x + p.y*p.y + p.z*p.z + p.w*p.w;
    float s2 = v.x*p.x + v.y*p.y + v.z*p.z + v.w*p.w;
    #pragma unroll
    for (int o = 16; o > 0; o >>= 1) {
        s0 += __shfl_xor_sync(0xFFFFFFFFu, s0, o);
        s1 += __shfl_xor_sync(0xFFFFFFFFu, s1, o);
        s2 += __shfl_xor_sync(0xFFFFFFFFu, s2, o);
    }
    float invA = 1.0f / fmaxf(sqrtf(s0), 1e-8f);
    float invB = 1.0f / fmaxf(sqrtf(s1), 1e-8f);
    float sa = invA * SQRT_EXP_SCALE;
    float sb = invB * SQRT_EXP_SCALE;

    uint2 oa, ob;
    {
        __nv_bfloat162 h0 = __float22bfloat162_rn(make_float2(v.x * sa, v.y * sa));
        __nv_bfloat162 h1 = __float22bfloat162_rn(make_float2(v.z * sa, v.w * sa));
        oa.x = *(uint32_t*)&h0; oa.y = *(uint32_t*)&h1;
        __nv_bfloat162 g0 = __float22bfloat162_rn(make_float2(p.x * sb, p.y * sb));
        __nv_bfloat162 g1 = __float22bfloat162_rn(make_float2(p.z * sb, p.w * sb));
        ob.x = *(uint32_t*)&g0; ob.y = *(uint32_t*)&g1;
    }
    ((uint2*)(g_nrep_bf16 + (size_t)j * ZD))[lane] = oa;
    ((uint2*)(g_nrep_bf16 + (size_t)(j + TWO_N/2) * ZD))[lane] = ob;

    if (lane == 0) {
        float pos = s2 * invA * invB;
        g_pos[j] = pos;
        g_pos[j + TWO_N/2] = pos;
        g_rowsum[j] = 0.0f;
        g_rowsum[j + TWO_N/2] = 0.0f;
        if (j == 0) g_ticket = 0u;
    }
}

// ---------------------------------------------------------------------------
// cp.async loaders. Full B strip: 512 threads. Quarter A strip: 128 threads.
// ---------------------------------------------------------------------------
__device__ __forceinline__ void load_b(__nv_bfloat16* dst, int rowBase, int tid) {
    #pragma unroll
    for (int it = 0; it < 4; it++) {
        int i2 = it * 512 + tid;          // 2048 16B-chunks
        int rr = i2 >> 4, c = i2 & 15;
        uint32_t d = (uint32_t)__cvta_generic_to_shared(dst + rr * STRIDE + c * 8);
        const void* g = g_nrep_bf16 + (size_t)(rowBase + rr) * ZD + c * 8;
        asm volatile("cp.async.cg.shared.global [%0], [%1], 16;" :: "r"(d), "l"(g));
    }
}
__device__ __forceinline__ void load_a_q(__nv_bfloat16* dst, int rowBase, int qtid) {
    #pragma unroll
    for (int it = 0; it < 4; it++) {
        int i2 = it * 128 + qtid;         // 512 16B-chunks (32 rows)
        int rr = i2 >> 4, c = i2 & 15;
        uint32_t d = (uint32_t)__cvta_generic_to_shared(dst + rr * STRIDE + c * 8);
        const void* g = g_nrep_bf16 + (size_t)(rowBase + rr) * ZD + c * 8;
        asm volatile("cp.async.cg.shared.global [%0], [%1], 16;" :: "r"(d), "l"(g));
    }
}

// ---------------------------------------------------------------------------
// Per-tile epilogue (DIAG templated): ex2 of acc (scale pre-folded), optional
// self-diag mask; accumulation in PACKED f32x2 (halves FADD issue count and
// serial chain depth); row flush = 2 SHFL + ONE red.global per row; column
// sums ride in packed colacc registers.
// ---------------------------------------------------------------------------
template<bool DIAG>
__device__ __forceinline__ void epilogue(float (&acc)[2][4][4],
                                         unsigned long long (&colacc)[4],
                                         int rowBase, int colBase,
                                         int wn, int lane) {
    int g = lane >> 2, t = lane & 3;

    #pragma unroll
    for (int mt = 0; mt < 2; mt++) {
        #pragma unroll
        for (int hh = 0; hh < 2; hh++) {
            int i = rowBase + mt * 16 + hh * 8 + g;
            unsigned long long s2p = 0ull;   // packed (f32, f32) zero
            #pragma unroll
            for (int nt = 0; nt < 4; nt++) {
                float e0, e1;
                asm("ex2.approx.f32 %0, %1;" : "=f"(e0)
                    : "f"(acc[mt][nt][hh * 2 + 0]));
                asm("ex2.approx.f32 %0, %1;" : "=f"(e1)
                    : "f"(acc[mt][nt][hh * 2 + 1]));
                if (DIAG) {
                    int j0 = colBase + wn * 32 + t * 2 + nt * 8;
                    if (i == j0)     e0 = 0.0f;
                    if (i == j0 + 1) e1 = 0.0f;
                }
                unsigned long long pr;
                asm("mov.b64 %0, {%1, %2};" : "=l"(pr) : "f"(e0), "f"(e1));
                asm("add.rn.f32x2 %0, %0, %1;" : "+l"(s2p) : "l"(pr));
                if (!DIAG)
                    asm("add.rn.f32x2 %0, %0, %1;" : "+l"(colacc[nt]) : "l"(pr));
            }
            float slo, shi;
            asm("mov.b64 {%0, %1}, %2;" : "=f"(slo), "=f"(shi) : "l"(s2p));
            float s = slo + shi;
            s += __shfl_xor_sync(0xFFFFFFFFu, s, 1);
            s += __shfl_xor_sync(0xFFFFFFFFu, s, 2);
            if (t == 0)
                asm volatile("red.global.add.f32 [%0], %1;"
                             :: "l"(&g_rowsum[i]), "f"(s) : "memory");
        }
    }
}

// Flush accumulated (packed) column sums for column strip colBase, zero them.
__device__ __forceinline__ void flush_colacc(unsigned long long (&colacc)[4],
                                             int colBase, int wn, int lane) {
    int g = lane >> 2, t = lane & 3;
    float cv[8];
    #pragma unroll
    for (int c = 0; c < 4; c++) {
        asm("mov.b64 {%0, %1}, %2;" : "=f"(cv[2*c]), "=f"(cv[2*c+1]) : "l"(colacc[c]));
        colacc[c] = 0ull;
    }
    #pragma unroll
    for (int c = 0; c < 8; c++) {
        float v = cv[c];
        v += __shfl_xor_sync(0xFFFFFFFFu, v, 4);
        v += __shfl_xor_sync(0xFFFFFFFFu, v, 8);
        v += __shfl_xor_sync(0xFFFFFFFFu, v, 16);
        cv[c] = v;
    }
    if (g == 0) {
        int jbase = colBase + wn * 32 + t * 2;
        #pragma unroll
        for (int c = 0; c < 8; c++) {
            int j = jbase + (c >> 1) * 8 + (c & 1);
            asm volatile("red.global.add.f32 [%0], %1;"
                         :: "l"(&g_rowsum[j]), "f"(cv[c]) : "memory");
        }
    }
}

// ---------------------------------------------------------------------------
// Kernel 2: PERSISTENT fused sim GEMM, column-major triangle walk, CTA split
// into FOUR independent 128-thread groups (named barriers). Each group owns
// a 32-row A strip (own double buffer); B (column strip) is shared, reloaded
// at column transitions under a full __syncthreads. 8 decoupled streams per
// SM; each SMSP hosts one warp from each stream.
// ---------------------------------------------------------------------------
__global__ void __launch_bounds__(512, 2) simgemm_kernel(float* __restrict__ out) {
    extern __shared__ __nv_bfloat16 smem[];
    __nv_bfloat16* sB = smem;                            // full column strip
    int tid = threadIdx.x;
    int wid = tid >> 5, lane = tid & 31;
    int grp = wid >> 2;                  // group 0..3 (owns rows grp*32..+32)
    int wn  = wid & 3;                   // n-warp within group (SMSP spread)
    int qtid = tid & 127;                // thread within group
    __nv_bfloat16* sA = smem + B_ELEMS + grp * 2 * Q_ELEMS;  // parity buffers

    // Contiguous chunk in column-major triangle order
    const int base = NUM_TILES / NUM_CTAS;      // 6
    const int rem  = NUM_TILES % NUM_CTAS;      // 256
    int bidx = blockIdx.x;
    int start = bidx * base + (bidx < rem ? bidx : rem);
    int count = base + (bidx < rem ? 1 : 0);

    // Decode start -> (tx, ty): column tx holds tiles ty in [0, tx]
    int tx = (int)((sqrtf(8.0f * (float)start + 1.0f) - 1.0f) * 0.5f);
    while (tx * (tx + 1) / 2 > start) tx--;
    while ((tx + 1) * (tx + 2) / 2 <= start) tx++;
    int ty = start - tx * (tx + 1) / 2;

    // Initial loads: B(tx) by all threads, A quarter by each group; one group
    load_b(sB, tx * BN, tid);
    load_a_q(sA, ty * BM + grp * 32, qtid);
    asm volatile("cp.async.commit_group;" ::: "memory");

    // ldmatrix base addresses (per lane); A offset adds parity*Q_BYTES
    uint32_t aAddr[2];
    #pragma unroll
    for (int mt = 0; mt < 2; mt++) {
        int row = mt * 16 + (lane & 15);                 // 0..31 in strip
        int k = (lane >> 4) * 8;
        aAddr[mt] = (uint32_t)__cvta_generic_to_shared(sA + row * STRIDE + k);
    }
    uint32_t bAddr[2];
    #pragma unroll
    for (int ntp = 0; ntp < 2; ntp++) {
        int n = wn * 32 + ntp * 16 + ((lane >> 4) & 1) * 8 + (lane & 7);
        int k = ((lane >> 3) & 1) * 8;
        bAddr[ntp] = (uint32_t)__cvta_generic_to_shared(sB + n * STRIDE + k);
    }

    unsigned long long colacc[4];
    #pragma unroll
    for (int c = 0; c < 4; c++) colacc[c] = 0ull;

    int barid = 1 + grp;    // named barrier per group (0 reserved for CTA)

    #pragma unroll 1
    for (int t = 0; t < count; t++) {
        uint32_t aOff = (uint32_t)(t & 1) * Q_BYTES;
        int nty = ty + 1, ntx = tx;
        if (nty > tx) { ntx = tx + 1; nty = 0; }
        bool more = (t + 1 < count);

        // Wait for this tile's A (+B at transitions); prefetched -> usually free
        asm volatile("cp.async.wait_group 0;" ::: "memory");
        asm volatile("bar.sync %0, 128;" :: "r"(barid) : "memory");

        // Same column: prefetch this group's next A into the alternate buffer
        if (more && ntx == tx) {
            load_a_q(sA + ((t + 1) & 1) * Q_ELEMS, nty * BM + grp * 32, qtid);
            asm volatile("cp.async.commit_group;" ::: "memory");
        }

        float acc[2][4][4];
        #pragma unroll
        for (int mt = 0; mt < 2; mt++)
            #pragma unroll
            for (int nt = 0; nt < 4; nt++)
                #pragma unroll
                for (int e = 0; e < 4; e++) acc[mt][nt][e] = 0.0f;

        // ---- Mainloop: 8 k-steps of k16
        #pragma unroll
        for (int ks = 0; ks < 8; ks++) {
            uint32_t a[2][4];
            #pragma unroll
            for (int mt = 0; mt < 2; mt++)
                asm volatile("ldmatrix.sync.aligned.m8n8.x4.shared.b16 {%0,%1,%2,%3}, [%4];"
                    : "=r"(a[mt][0]), "=r"(a[mt][1]), "=r"(a[mt][2]), "=r"(a[mt][3])
                    : "r"(aAddr[mt] + aOff + ks * 32));
            uint32_t b[4][2];
            #pragma unroll
            for (int ntp = 0; ntp < 2; ntp++)
                asm volatile("ldmatrix.sync.aligned.m8n8.x4.shared.b16 {%0,%1,%2,%3}, [%4];"
                    : "=r"(b[2*ntp][0]), "=r"(b[2*ntp][1]),
                      "=r"(b[2*ntp+1][0]), "=r"(b[2*ntp+1][1])
                    : "r"(bAddr[ntp] + ks * 32));
            #pragma unroll
            for (int mt = 0; mt < 2; mt++)
                #pragma unroll
                for (int nt = 0; nt < 4; nt++)
                    asm volatile(
                        "mma.sync.aligned.m16n8k16.row.col.f32.bf16.bf16.f32 "
                        "{%0,%1,%2,%3}, {%4,%5,%6,%7}, {%8,%9}, {%0,%1,%2,%3};"
                        : "+f"(acc[mt][nt][0]), "+f"(acc[mt][nt][1]),
                          "+f"(acc[mt][nt][2]), "+f"(acc[mt][nt][3])
                        : "r"(a[mt][0]), "r"(a[mt][1]), "r"(a[mt][2]), "r"(a[mt][3]),
                          "r"(b[nt][0]), "r"(b[nt][1]));
        }

        int rowBase = ty * BM + grp * 32;
        if (ty == tx) {
            epilogue<true >(acc, colacc, rowBase, tx * BN, wn, lane);
            flush_colacc(colacc, tx * BN, wn, lane);   // column complete
        } else {
            epilogue<false>(acc, colacc, rowBase, tx * BN, wn, lane);
        }

        // Column transition: rejoin the full CTA, reload B (+ own A quarter)
        if (more && ntx != tx) {
            __syncthreads();
            load_b(sB, ntx * BN, tid);
            load_a_q(sA + ((t + 1) & 1) * Q_ELEMS, nty * BM + grp * 32, qtid);
            asm volatile("cp.async.commit_group;" ::: "memory");
        }
        ty = nty; tx = ntx;
    }

    // Flush any partial column left at chunk end (zeros if already flushed)
    flush_colacc(colacc, (ty == 0 ? tx - 1 : tx) * BN, wn, lane);

    // ---- Ticket: last CTA computes the scalar loss (fast log2)
    __shared__ bool is_last;
    __syncthreads();
    if (tid == 0) {
        __threadfence();
        unsigned int tk = atomicInc(&g_ticket, 0xFFFFFFFFu);
        is_last = (tk == (unsigned int)(NUM_CTAS - 1));
    }
    __syncthreads();
    if (is_last) {
        __threadfence();
        float acc2 = 0.0f;
        #pragma unroll 4
        for (int i = tid; i < TWO_N; i += 512)
            acc2 += __log2f(__ldcg(&g_rowsum[i])) * LN2F - g_pos[i] * INV_T;
        #pragma unroll
        for (int o = 16; o > 0; o >>= 1)
            acc2 += __shfl_xor_sync(0xFFFFFFFFu, acc2, o);
        __shared__ float sred[16];
        if ((tid & 31) == 0) sred[tid >> 5] = acc2;
        __syncthreads();
        if (tid == 0) {
            float tot = 0.0f;
            #pragma unroll
            for (int w = 0; w < 16; w++) tot += sred[w];
            out[0] = tot * (1.0f / (float)TWO_N);
        }
    }
}

// ---------------------------------------------------------------------------
extern "C" void kernel_launch(void* const* d_in, const int* in_sizes, int n_in,
                              void* d_out, int out_size) {
    const float* z1 = (const float*)d_in[0];
    const float* z2 = (const float*)d_in[1];

    cudaFuncSetAttribute(simgemm_kernel,
                         cudaFuncAttributeMaxDynamicSharedMemorySize, SMEM_SZ);

    normalize_pos_kernel<<<512, 256>>>(z1, z2);
    simgemm_kernel<<<NUM_CTAS, 512, SMEM_SZ>>>((float*)d_out);
}